// round 8
// baseline (speedup 1.0000x reference)
#include <cuda_runtime.h>
#include <cuda_bf16.h>
#include <math.h>
#include <stdint.h>

#define TT 50
#define BB 256
#define DBEL 1024
#define DST 128
#define DACT 32
#define DHID 1024
#define DEMB 1024
#define GRU3 (3*DBEL)

// ---- output layout (beliefs, prior_s, mp, sp, post_s, mq, sq) ----
static constexpr size_t OFF_BEL = 0;
static constexpr size_t OFF_PRS = (size_t)TT*BB*DBEL;
static constexpr size_t OFF_MP  = OFF_PRS + (size_t)TT*BB*DST;
static constexpr size_t OFF_SP  = OFF_MP  + (size_t)TT*BB*DST;
static constexpr size_t OFF_POS = OFF_SP  + (size_t)TT*BB*DST;
static constexpr size_t OFF_MQ  = OFF_POS + (size_t)TT*BB*DST;
static constexpr size_t OFF_SQ  = OFF_MQ  + (size_t)TT*BB*DST;

// ---- fp32 scratch ----
__device__ float g_x[BB*DBEL];
__device__ float g_gi[BB*GRU3];
__device__ float g_gh[BB*GRU3];
__device__ float g_belief[BB*DBEL];
__device__ float g_hq[BB*DHID];
__device__ float g_hp[(size_t)TT*BB*DHID];

// ---- bf16 hi/lo weight planes ----
__device__ __nv_bfloat16 g_wsa_h[DBEL*(DST+DACT)],   g_wsa_l[DBEL*(DST+DACT)];
__device__ __nv_bfloat16 g_wih_h[GRU3*DBEL],         g_wih_l[GRU3*DBEL];
__device__ __nv_bfloat16 g_whh_h[GRU3*DBEL],         g_whh_l[GRU3*DBEL];
__device__ __nv_bfloat16 g_wpoh_h[DHID*(DBEL+DEMB)], g_wpoh_l[DHID*(DBEL+DEMB)];
__device__ __nv_bfloat16 g_wpos_h[2*DST*DHID],       g_wpos_l[2*DST*DHID];
__device__ __nv_bfloat16 g_wprh_h[DHID*DBEL],        g_wprh_l[DHID*DBEL];
__device__ __nv_bfloat16 g_wprs_h[2*DST*DHID],       g_wprs_l[2*DST*DHID];

// ---- grid barrier state (zero-initialized at module load; count invariant 0 between barriers) ----
__device__ unsigned g_bar_count;
__device__ unsigned g_bar_gen;

__device__ __forceinline__ float eluf(float x)   { return x > 0.f ? x : expm1f(x); }
__device__ __forceinline__ float splusf(float x) { return fmaxf(x, 0.f) + log1pf(expf(-fabsf(x))); }
__device__ __forceinline__ float sigf(float x)   { return 1.f / (1.f + expf(-x)); }

__device__ __forceinline__ void grid_barrier(int nblk)
{
    __syncthreads();
    if (threadIdx.x == 0) {
        unsigned gen = *((volatile unsigned*)&g_bar_gen);
        __threadfence();
        unsigned old = atomicAdd(&g_bar_count, 1u);
        if (old == (unsigned)(nblk - 1)) {
            g_bar_count = 0u;
            __threadfence();
            atomicAdd(&g_bar_gen, 1u);
        } else {
            while (*((volatile unsigned*)&g_bar_gen) == gen) __nanosleep(64);
        }
        __threadfence();
    }
    __syncthreads();
}

// ================= GEMM core =================
enum { ALOAD_PLAIN = 0, ALOAD_ELU = 1, ALOAD_STATE = 2 };
enum { EPI_BIAS = 0, EPI_BIAS_ELU = 1, EPI_ATOMIC = 2, EPI_HEAD_ATOMIC = 3, EPI_HEAD_STORE = 4 };

struct Smem {
    __nv_bfloat16 A[2][2][64*40];   // [stage][plane hi/lo][64 rows x 40 cols]
    __nv_bfloat16 B[2][2][64*40];
};

// A loads from mutable cross-phase buffers use __ldcg: L1 is NOT coherent across SMs and
// the software barrier does not flush L1 (a kernel boundary would).
template<int ALOAD>
__device__ __forceinline__ void load_a8(
    int gm, int k, float* r,
    const float* A1, int lda1, const float* A2, int lda2, int K1,
    const float* st_mq, const float* st_sq, const float* st_eps,
    const float* st_nt, const float* st_prev)
{
    if (ALOAD == ALOAD_STATE && k < K1) {
        const float nt = st_nt[gm];
        const int base = gm * DST + k;
        if (st_mq) {
#pragma unroll
            for (int i = 0; i < 8; i++) {
                float mq = __ldcg(st_mq + base + i);
                float sq = __ldcg(st_sq + base + i);
                float s = splusf(sq) + 0.1f;
                r[i] = (mq + s * __ldg(st_eps + base + i)) * nt;
            }
        } else {
#pragma unroll
            for (int i = 0; i < 8; i++) r[i] = __ldg(st_prev + base + i) * nt;
        }
        return;
    }
    const float* p;
    if (k < K1) p = A1 + (size_t)gm * lda1 + k;
    else        p = A2 + (size_t)gm * lda2 + (k - K1);
    float4 v0 = __ldcg(reinterpret_cast<const float4*>(p));
    float4 v1 = __ldcg(reinterpret_cast<const float4*>(p + 4));
    r[0] = v0.x; r[1] = v0.y; r[2] = v0.z; r[3] = v0.w;
    r[4] = v1.x; r[5] = v1.y; r[6] = v1.z; r[7] = v1.w;
    if (ALOAD == ALOAD_ELU) {
#pragma unroll
        for (int i = 0; i < 8; i++) r[i] = eluf(r[i]);
    }
}

__device__ __forceinline__ void split_pack8(const float* r, uint4& h, uint4& l)
{
    uint32_t hw[4], lw[4];
#pragma unroll
    for (int i = 0; i < 4; i++) {
        __nv_bfloat16 h0 = __float2bfloat16_rn(r[2*i]);
        __nv_bfloat16 h1 = __float2bfloat16_rn(r[2*i+1]);
        __nv_bfloat16 l0 = __float2bfloat16_rn(r[2*i]   - __bfloat162float(h0));
        __nv_bfloat16 l1 = __float2bfloat16_rn(r[2*i+1] - __bfloat162float(h1));
        __nv_bfloat162 hp = __halves2bfloat162(h0, h1);
        __nv_bfloat162 lp = __halves2bfloat162(l0, l1);
        hw[i] = *reinterpret_cast<uint32_t*>(&hp);
        lw[i] = *reinterpret_cast<uint32_t*>(&lp);
    }
    h = make_uint4(hw[0], hw[1], hw[2], hw[3]);
    l = make_uint4(lw[0], lw[1], lw[2], lw[3]);
}

__device__ __forceinline__ void ldsm4(uint32_t (&r)[4], uint32_t addr) {
    asm volatile("ldmatrix.sync.aligned.m8n8.x4.shared.b16 {%0,%1,%2,%3}, [%4];"
        : "=r"(r[0]), "=r"(r[1]), "=r"(r[2]), "=r"(r[3]) : "r"(addr));
}
__device__ __forceinline__ void ldsm2(uint32_t (&r)[2], uint32_t addr) {
    asm volatile("ldmatrix.sync.aligned.m8n8.x2.shared.b16 {%0,%1}, [%2];"
        : "=r"(r[0]), "=r"(r[1]) : "r"(addr));
}
__device__ __forceinline__ void mma16816(float (&d)[4], const uint32_t (&a)[4], const uint32_t (&b)[2]) {
    asm volatile("mma.sync.aligned.m16n8k16.row.col.f32.bf16.bf16.f32 "
        "{%0,%1,%2,%3}, {%4,%5,%6,%7}, {%8,%9}, {%0,%1,%2,%3};"
        : "+f"(d[0]), "+f"(d[1]), "+f"(d[2]), "+f"(d[3])
        : "r"(a[0]), "r"(a[1]), "r"(a[2]), "r"(a[3]), "r"(b[0]), "r"(b[1]));
}

template<int EPI>
__device__ __forceinline__ void epi_pair(
    int kc, int r, int c, float v0, float v1,
    const float* bias, float* out, int ldout, float* mean_out, float* std_out)
{
    if (EPI == EPI_BIAS) {
        float2 o = make_float2(v0 + __ldg(bias + c), v1 + __ldg(bias + c + 1));
        *reinterpret_cast<float2*>(out + (size_t)r * ldout + c) = o;
    } else if (EPI == EPI_BIAS_ELU) {
        float2 o = make_float2(eluf(v0 + __ldg(bias + c)), eluf(v1 + __ldg(bias + c + 1)));
        *reinterpret_cast<float2*>(out + (size_t)r * ldout + c) = o;
    } else if (EPI == EPI_ATOMIC) {
        float* o = out + (size_t)r * ldout + c;
        atomicAdd(o, v0); atomicAdd(o + 1, v1);
    } else if (EPI == EPI_HEAD_ATOMIC) {
        float b0 = (kc == 0) ? __ldg(bias + c)     : 0.f;
        float b1 = (kc == 0) ? __ldg(bias + c + 1) : 0.f;
        if (c < DST) {
            atomicAdd(mean_out + (size_t)r * DST + c,     v0 + b0);
            atomicAdd(mean_out + (size_t)r * DST + c + 1, v1 + b1);
        } else {
            atomicAdd(std_out + (size_t)r * DST + (c - DST),     v0 + b0);
            atomicAdd(std_out + (size_t)r * DST + (c - DST) + 1, v1 + b1);
        }
    } else { // EPI_HEAD_STORE
        float w0 = v0 + __ldg(bias + c), w1 = v1 + __ldg(bias + c + 1);
        if (c < DST) {
            mean_out[(size_t)r * DST + c]     = w0;
            mean_out[(size_t)r * DST + c + 1] = w1;
        } else {
            std_out[(size_t)r * DST + (c - DST)]     = splusf(w0) + 0.1f;
            std_out[(size_t)r * DST + (c - DST) + 1] = splusf(w1) + 0.1f;
        }
    }
}

template<int KC, int ALOAD, int EPI>
__device__ void gemm_tile(
    Smem* sm, int mb, int nb, int kc,
    const float* A1, int lda1, const float* A2, int lda2, int K1,
    const __nv_bfloat16* __restrict__ Wh, const __nv_bfloat16* __restrict__ Wl, int ldw,
    const float* __restrict__ bias, float* out, int ldout,
    float* mean_out, float* std_out,
    const float* st_mq, const float* st_sq, const float* st_eps,
    const float* st_nt, const float* st_prev)
{
    constexpr int NST = KC / 32;
    const int kbeg = kc * KC;

    const int tid  = threadIdx.x;
    const int lrow = tid >> 2;
    const int lk   = (tid & 3) << 3;
    const int gm   = mb * 64 + lrow;
    const int gn   = nb * 64 + lrow;

    const int lane = tid & 31;
    const int wid  = tid >> 5;
    const int wm = (wid >> 2) * 32;
    const int wn = (wid & 3) * 16;

    const int amat = lane >> 3, arin = lane & 7;
    const int arow = wm + ((amat & 1) << 3) + arin;
    const int acol = (amat >> 1) << 3;
    const int brin = lane & 7;
    const int bmat = (lane >> 3) & 1;

    const uint32_t aBase = (uint32_t)__cvta_generic_to_shared(&sm->A[0][0][0]);
    const uint32_t bBase = (uint32_t)__cvta_generic_to_shared(&sm->B[0][0][0]);
    const uint32_t STG = 2u * 64 * 40 * 2;
    const uint32_t PLN = 64u * 40 * 2;

    __syncthreads();   // previous tile's last compute fully done before reusing buffers

    float ra[8]; uint4 rbh, rbl;
    load_a8<ALOAD>(gm, kbeg + lk, ra, A1, lda1, A2, lda2, K1, st_mq, st_sq, st_eps, st_nt, st_prev);
    rbh = __ldg(reinterpret_cast<const uint4*>(Wh + (size_t)gn * ldw + kbeg + lk));
    rbl = __ldg(reinterpret_cast<const uint4*>(Wl + (size_t)gn * ldw + kbeg + lk));
    {
        uint4 ah, al; split_pack8(ra, ah, al);
        *reinterpret_cast<uint4*>(&sm->A[0][0][lrow*40 + lk]) = ah;
        *reinterpret_cast<uint4*>(&sm->A[0][1][lrow*40 + lk]) = al;
        *reinterpret_cast<uint4*>(&sm->B[0][0][lrow*40 + lk]) = rbh;
        *reinterpret_cast<uint4*>(&sm->B[0][1][lrow*40 + lk]) = rbl;
    }
    __syncthreads();

    float acc[2][2][4];
#pragma unroll
    for (int i = 0; i < 2; i++)
#pragma unroll
        for (int j = 0; j < 2; j++)
#pragma unroll
            for (int q = 0; q < 4; q++) acc[i][j][q] = 0.f;

#pragma unroll 1
    for (int t = 0; t < NST; t++) {
        const int cur = t & 1;
        const bool more = (t + 1 < NST);
        if (more) {
            int k = kbeg + (t + 1) * 32 + lk;
            load_a8<ALOAD>(gm, k, ra, A1, lda1, A2, lda2, K1, st_mq, st_sq, st_eps, st_nt, st_prev);
            rbh = __ldg(reinterpret_cast<const uint4*>(Wh + (size_t)gn * ldw + k));
            rbl = __ldg(reinterpret_cast<const uint4*>(Wl + (size_t)gn * ldw + k));
        }
        const uint32_t aOff = aBase + cur * STG;
        const uint32_t bOff = bBase + cur * STG;
#pragma unroll
        for (int kk = 0; kk < 32; kk += 16) {
            uint32_t Ah[2][4], Al[2][4], Bh[2][2], Bl[2][2];
#pragma unroll
            for (int mf = 0; mf < 2; mf++) {
                uint32_t off = (uint32_t)(((arow + mf*16) * 40 + kk + acol) * 2);
                ldsm4(Ah[mf], aOff + off);
                ldsm4(Al[mf], aOff + PLN + off);
            }
#pragma unroll
            for (int nf = 0; nf < 2; nf++) {
                uint32_t off = (uint32_t)(((wn + nf*8 + brin) * 40 + kk + bmat*8) * 2);
                ldsm2(Bh[nf], bOff + off);
                ldsm2(Bl[nf], bOff + PLN + off);
            }
#pragma unroll
            for (int mf = 0; mf < 2; mf++)
#pragma unroll
                for (int nf = 0; nf < 2; nf++) {
                    mma16816(acc[mf][nf], Ah[mf], Bh[nf]);
                    mma16816(acc[mf][nf], Ah[mf], Bl[nf]);
                    mma16816(acc[mf][nf], Al[mf], Bh[nf]);
                }
        }
        if (more) {
            const int nxt = cur ^ 1;
            uint4 ah, al; split_pack8(ra, ah, al);
            *reinterpret_cast<uint4*>(&sm->A[nxt][0][lrow*40 + lk]) = ah;
            *reinterpret_cast<uint4*>(&sm->A[nxt][1][lrow*40 + lk]) = al;
            *reinterpret_cast<uint4*>(&sm->B[nxt][0][lrow*40 + lk]) = rbh;
            *reinterpret_cast<uint4*>(&sm->B[nxt][1][lrow*40 + lk]) = rbl;
        }
        __syncthreads();   // single sync per stage
    }

    const int gr = lane >> 2, gc = (lane & 3) << 1;
#pragma unroll
    for (int mf = 0; mf < 2; mf++)
#pragma unroll
        for (int nf = 0; nf < 2; nf++) {
            int r = mb * 64 + wm + mf * 16 + gr;
            int c = nb * 64 + wn + nf * 8 + gc;
            epi_pair<EPI>(kc, r,     c, acc[mf][nf][0], acc[mf][nf][1], bias, out, ldout, mean_out, std_out);
            epi_pair<EPI>(kc, r + 8, c, acc[mf][nf][2], acc[mf][nf][3], bias, out, ldout, mean_out, std_out);
        }
}

// ================= elementwise phases =================
__device__ void conv_seg(const float* __restrict__ s, __nv_bfloat16* hi, __nv_bfloat16* lo,
                         int n, int gtid, int nthr)
{
    for (int i = gtid * 4; i < n; i += nthr * 4) {
        float4 v = __ldg(reinterpret_cast<const float4*>(s + i));
        float vv[4] = {v.x, v.y, v.z, v.w};
        __nv_bfloat16 h[4], l[4];
#pragma unroll
        for (int j = 0; j < 4; j++) {
            h[j] = __float2bfloat16_rn(vv[j]);
            l[j] = __float2bfloat16_rn(vv[j] - __bfloat162float(h[j]));
        }
        *reinterpret_cast<__nv_bfloat162*>(hi + i)     = __halves2bfloat162(h[0], h[1]);
        *reinterpret_cast<__nv_bfloat162*>(hi + i + 2) = __halves2bfloat162(h[2], h[3]);
        *reinterpret_cast<__nv_bfloat162*>(lo + i)     = __halves2bfloat162(l[0], l[1]);
        *reinterpret_cast<__nv_bfloat162*>(lo + i + 2) = __halves2bfloat162(l[2], l[3]);
    }
}

__device__ void phase_gru(const float* __restrict__ b_poh, float* bel_out, int gtid, int nthr)
{
    for (int i4 = gtid * 4; i4 < BB * DBEL; i4 += nthr * 4) {
        int m = i4 >> 10, j = i4 & 1023;
        const float* gi = g_gi + (size_t)m * GRU3 + j;
        const float* gh = g_gh + (size_t)m * GRU3 + j;
        float4 gir = __ldcg(reinterpret_cast<const float4*>(gi));
        float4 giz = __ldcg(reinterpret_cast<const float4*>(gi + 1024));
        float4 gin = __ldcg(reinterpret_cast<const float4*>(gi + 2048));
        float4 ghr = __ldcg(reinterpret_cast<const float4*>(gh));
        float4 ghz = __ldcg(reinterpret_cast<const float4*>(gh + 1024));
        float4 ghn = __ldcg(reinterpret_cast<const float4*>(gh + 2048));
        float4 b   = __ldcg(reinterpret_cast<const float4*>(g_belief + i4));
        float4 h;
        { float r = sigf(gir.x + ghr.x), z = sigf(giz.x + ghz.x);
          h.x = (1.f - z) * tanhf(gin.x + r * ghn.x) + z * b.x; }
        { float r = sigf(gir.y + ghr.y), z = sigf(giz.y + ghz.y);
          h.y = (1.f - z) * tanhf(gin.y + r * ghn.y) + z * b.y; }
        { float r = sigf(gir.z + ghr.z), z = sigf(giz.z + ghz.z);
          h.z = (1.f - z) * tanhf(gin.z + r * ghn.z) + z * b.z; }
        { float r = sigf(gir.w + ghr.w), z = sigf(giz.w + ghz.w);
          h.w = (1.f - z) * tanhf(gin.w + r * ghn.w) + z * b.w; }
        *reinterpret_cast<float4*>(g_belief + i4) = h;
        *reinterpret_cast<float4*>(bel_out + i4)  = h;
        *reinterpret_cast<float4*>(g_hq + i4) = __ldg(reinterpret_cast<const float4*>(b_poh + j));
    }
}

// ================= megakernel =================
struct Params {
    const float *prev_state, *actions, *prev_belief, *observations, *nonterminals,
                *prior_noise, *post_noise;
    const float *W_sa, *b_sa, *w_ih, *b_ih, *w_hh, *b_hh,
                *W_prh, *b_prh, *W_prs, *b_prs, *W_poh, *b_poh, *W_pos, *b_pos;
    float* out;
    int nblk;
};

__global__ void __launch_bounds__(256) mega(Params P)
{
    __shared__ Smem sm;
    const int nblk = P.nblk;
    const int bid  = blockIdx.x;
    const int gtid = bid * 256 + threadIdx.x;
    const int nthr = nblk * 256;
    float* out = P.out;

    // ---- phase 0: weight split-convert + init ----
    conv_seg(P.W_sa,  g_wsa_h,  g_wsa_l,  DBEL*(DST+DACT),   gtid, nthr);
    conv_seg(P.w_ih,  g_wih_h,  g_wih_l,  GRU3*DBEL,         gtid, nthr);
    conv_seg(P.w_hh,  g_whh_h,  g_whh_l,  GRU3*DBEL,         gtid, nthr);
    conv_seg(P.W_poh, g_wpoh_h, g_wpoh_l, DHID*(DBEL+DEMB),  gtid, nthr);
    conv_seg(P.W_pos, g_wpos_h, g_wpos_l, 2*DST*DHID,        gtid, nthr);
    conv_seg(P.W_prh, g_wprh_h, g_wprh_l, DHID*DBEL,         gtid, nthr);
    conv_seg(P.W_prs, g_wprs_h, g_wprs_l, 2*DST*DHID,        gtid, nthr);
    for (int i = gtid * 4; i < BB * DBEL; i += nthr * 4)
        *reinterpret_cast<float4*>(g_belief + i) =
            __ldg(reinterpret_cast<const float4*>(P.prev_belief + i));
    {
        float4 z4 = make_float4(0.f, 0.f, 0.f, 0.f);
        for (int i = gtid * 4; i < 2 * TT * BB * DST; i += nthr * 4)
            *reinterpret_cast<float4*>(out + OFF_MQ + i) = z4;
    }
    grid_barrier(nblk);

    // ---- the scan ----
    for (int t = 0; t < TT; t++) {
        const float* act = P.actions      + (size_t)t * BB * DACT;
        const float* obs = P.observations + (size_t)t * BB * DEMB;
        const float* snt = P.nonterminals + (size_t)t * BB;
        const float* smq = (t == 0) ? nullptr : out + OFF_MQ + (size_t)(t-1) * BB * DST;
        const float* ssq = (t == 0) ? nullptr : out + OFF_SQ + (size_t)(t-1) * BB * DST;
        const float* sep = (t == 0) ? nullptr : P.post_noise + (size_t)(t-1) * BB * DST;

        // P_x: x = elu([state*nt, a] @ Wsa^T + b)   (64 tiles, K=160)
        for (int tile = bid; tile < 64; tile += nblk) {
            int mb = tile >> 4, nb = tile & 15;
            gemm_tile<160, ALOAD_STATE, EPI_BIAS_ELU>(&sm, mb, nb, 0,
                nullptr, 0, act, DACT, DST,
                g_wsa_h, g_wsa_l, DST + DACT, P.b_sa, g_x, DBEL, nullptr, nullptr,
                smq, ssq, sep, snt, P.prev_state);
        }
        grid_barrier(nblk);

        // P_gigh: gi = x@Wih^T+b ; gh = belief@Whh^T+b   (384 tiles, K=1024)
        for (int tile = bid; tile < 384; tile += nblk) {
            int job = tile >= 192;
            int r = tile - job * 192;
            int mb = r / 48, nb = r % 48;
            if (!job)
                gemm_tile<1024, ALOAD_PLAIN, EPI_BIAS>(&sm, mb, nb, 0,
                    g_x, DBEL, nullptr, 0, DBEL,
                    g_wih_h, g_wih_l, DBEL, P.b_ih, g_gi, GRU3, nullptr, nullptr,
                    nullptr, nullptr, nullptr, nullptr, nullptr);
            else
                gemm_tile<1024, ALOAD_PLAIN, EPI_BIAS>(&sm, mb, nb, 0,
                    g_belief, DBEL, nullptr, 0, DBEL,
                    g_whh_h, g_whh_l, DBEL, P.b_hh, g_gh, GRU3, nullptr, nullptr,
                    nullptr, nullptr, nullptr, nullptr, nullptr);
        }
        grid_barrier(nblk);

        // P_gru: combine -> belief; write beliefs output; seed g_hq with b_poh
        phase_gru(P.b_poh, out + OFF_BEL + (size_t)t * BB * DBEL, gtid, nthr);
        grid_barrier(nblk);

        // P_hq: hq += [h, obs] @ Wpoh^T   (128 tiles, split-K=2, K=2048)
        for (int tile = bid; tile < 128; tile += nblk) {
            int kc = tile >> 6;
            int r = tile & 63;
            int mb = r >> 4, nb = r & 15;
            gemm_tile<1024, ALOAD_PLAIN, EPI_ATOMIC>(&sm, mb, nb, kc,
                g_belief, DBEL, obs, DEMB, DBEL,
                g_wpoh_h, g_wpoh_l, DBEL + DEMB, nullptr, g_hq, DHID, nullptr, nullptr,
                nullptr, nullptr, nullptr, nullptr, nullptr);
        }
        grid_barrier(nblk);

        // P_ph: elu(hq) @ Wpos^T + b -> mq, sq_raw   (128 tiles, split-K=8)
        for (int tile = bid; tile < 128; tile += nblk) {
            int kc = tile >> 4;
            int r = tile & 15;
            int mb = r >> 2, nb = r & 3;
            gemm_tile<128, ALOAD_ELU, EPI_HEAD_ATOMIC>(&sm, mb, nb, kc,
                g_hq, DHID, nullptr, 0, DHID,
                g_wpos_h, g_wpos_l, DHID, P.b_pos, nullptr, 0,
                out + OFF_MQ + (size_t)t * BB * DST,
                out + OFF_SQ + (size_t)t * BB * DST,
                nullptr, nullptr, nullptr, nullptr, nullptr);
        }
        grid_barrier(nblk);
    }

    // ---- batched prior hidden: hp = elu(beliefs @ Wprh^T + b)  (3200 tiles) ----
    for (int tile = bid; tile < 3200; tile += nblk) {
        int mb = tile >> 4, nb = tile & 15;
        gemm_tile<1024, ALOAD_PLAIN, EPI_BIAS_ELU>(&sm, mb, nb, 0,
            out + OFF_BEL, DBEL, nullptr, 0, DBEL,
            g_wprh_h, g_wprh_l, DBEL, P.b_prh, g_hp, DHID, nullptr, nullptr,
            nullptr, nullptr, nullptr, nullptr, nullptr);
    }
    grid_barrier(nblk);

    // ---- batched prior head: hp @ Wprs^T + b -> mp, sp  (800 tiles) ----
    for (int tile = bid; tile < 800; tile += nblk) {
        int mb = tile >> 2, nb = tile & 3;
        gemm_tile<1024, ALOAD_PLAIN, EPI_HEAD_STORE>(&sm, mb, nb, 0,
            g_hp, DHID, nullptr, 0, DHID,
            g_wprs_h, g_wprs_l, DHID, P.b_prs, nullptr, 0,
            out + OFF_MP, out + OFF_SP,
            nullptr, nullptr, nullptr, nullptr, nullptr);
    }
    grid_barrier(nblk);

    // ---- samples: prior_s, post_s; finalize sq ----
    for (int i = gtid * 4; i < TT * BB * DST; i += nthr * 4) {
        float4 mp = *reinterpret_cast<const float4*>(out + OFF_MP + i);
        float4 sp = *reinterpret_cast<const float4*>(out + OFF_SP + i);
        float4 ep = __ldg(reinterpret_cast<const float4*>(P.prior_noise + i));
        float4 mq = __ldcg(reinterpret_cast<const float4*>(out + OFF_MQ + i));
        float4 sq = __ldcg(reinterpret_cast<const float4*>(out + OFF_SQ + i));
        float4 eq = __ldg(reinterpret_cast<const float4*>(P.post_noise + i));
        float4 prs, pos, sqo;
        prs.x = mp.x + sp.x * ep.x; prs.y = mp.y + sp.y * ep.y;
        prs.z = mp.z + sp.z * ep.z; prs.w = mp.w + sp.w * ep.w;
        sqo.x = splusf(sq.x) + 0.1f; sqo.y = splusf(sq.y) + 0.1f;
        sqo.z = splusf(sq.z) + 0.1f; sqo.w = splusf(sq.w) + 0.1f;
        pos.x = mq.x + sqo.x * eq.x; pos.y = mq.y + sqo.y * eq.y;
        pos.z = mq.z + sqo.z * eq.z; pos.w = mq.w + sqo.w * eq.w;
        *reinterpret_cast<float4*>(out + OFF_PRS + i) = prs;
        *reinterpret_cast<float4*>(out + OFF_SQ  + i) = sqo;
        *reinterpret_cast<float4*>(out + OFF_POS + i) = pos;
    }
}

extern "C" void kernel_launch(void* const* d_in, const int* in_sizes, int n_in,
                              void* d_out, int out_size)
{
    (void)in_sizes; (void)n_in; (void)out_size;
    Params P;
    P.prev_state   = (const float*)d_in[0];
    P.actions      = (const float*)d_in[1];
    P.prev_belief  = (const float*)d_in[2];
    P.observations = (const float*)d_in[3];
    P.nonterminals = (const float*)d_in[4];
    P.prior_noise  = (const float*)d_in[5];
    P.post_noise   = (const float*)d_in[6];
    P.W_sa  = (const float*)d_in[7];
    P.b_sa  = (const float*)d_in[8];
    P.w_ih  = (const float*)d_in[9];
    P.b_ih  = (const float*)d_in[10];
    P.w_hh  = (const float*)d_in[11];
    P.b_hh  = (const float*)d_in[12];
    P.W_prh = (const float*)d_in[13];
    P.b_prh = (const float*)d_in[14];
    P.W_prs = (const float*)d_in[15];
    P.b_prs = (const float*)d_in[16];
    P.W_poh = (const float*)d_in[17];
    P.b_poh = (const float*)d_in[18];
    P.W_pos = (const float*)d_in[19];
    P.b_pos = (const float*)d_in[20];
    P.out = (float*)d_out;

    int nsm = 0;
    cudaDeviceGetAttribute(&nsm, cudaDevAttrMultiProcessorCount, 0);
    if (nsm <= 0) nsm = 148;
    P.nblk = nsm;

    mega<<<nsm, 256>>>(P);
}